// round 14
// baseline (speedup 1.0000x reference)
#include <cuda_runtime.h>
#include <cuda_bf16.h>
#include <mma.h>
#include <math.h>
#include <stdint.h>

using namespace nvcuda;

// ---------------- problem constants ----------------
#define B_    32
#define CIN   1280
#define HH    28
#define WW    28
#define HW    784
#define A_    9
#define HID   128
#define M_    4096
#define MTOT  8192
#define AHW   7056
#define NPOS  (B_ * HW)        // 25088

// output layout
#define OFF_CONF   0
#define OFF_OFFS   8192
#define OFF_CLASS  24576
#define OFF_IOU    106496

// ---------------- scratch ----------------
__device__ __nv_bfloat16 g_fT_hi[(size_t)NPOS * CIN];   // [b*HW+p][k]
__device__ __nv_bfloat16 g_fT_lo[(size_t)NPOS * CIN];
__device__ __nv_bfloat16 g_W1hi[HID * CIN];             // [n][k]
__device__ __nv_bfloat16 g_W1lo[HID * CIN];
__device__ __nv_bfloat16 g_W2hi[80 * HID];              // rows 65..79 stay zero
__device__ __nv_bfloat16 g_W2lo[80 * HID];

// ---------------- helpers ----------------
__device__ __forceinline__ uint32_t smem_u32(const void* p) {
    uint32_t a;
    asm("{ .reg .u64 t; cvta.to.shared.u64 t, %1; cvt.u32.u64 %0, t; }"
        : "=r"(a) : "l"(p));
    return a;
}
__device__ __forceinline__ uint32_t PK(__nv_bfloat16 a, __nv_bfloat16 b) {
    unsigned short ua = *(unsigned short*)&a;
    unsigned short ub = *(unsigned short*)&b;
    return (uint32_t)ua | ((uint32_t)ub << 16);
}
__device__ __forceinline__ void cpa16(uint32_t dst, const void* src) {
    asm volatile("cp.async.ca.shared.global [%0], [%1], 16;" :: "r"(dst), "l"(src));
}
#define CP_COMMIT() asm volatile("cp.async.commit_group;" ::: "memory")
#define CP_WAIT0()  asm volatile("cp.async.wait_group 0;" ::: "memory")
#define CP_WAIT1()  asm volatile("cp.async.wait_group 1;" ::: "memory")
#define CP_WAIT2()  asm volatile("cp.async.wait_group 2;" ::: "memory")

__device__ __forceinline__ float sigmoidf_(float x) {
    return 1.0f / (1.0f + expf(-x));
}

// ---------------------------------------------------------------------------
// Kernel 1: prep = transpose/split + W1 split + W2 split  (IoU moved to GEMM)
// ---------------------------------------------------------------------------
#define TR_BLKS  (25 * 32)          // 800
#define W1_BLKS  160
#define W2_BLKS  9
#define PREP_BLKS (TR_BLKS + W1_BLKS + W2_BLKS)

#define TLD 36

__global__ void __launch_bounds__(256)
prep_kernel(const float* __restrict__ feat,
            const float* __restrict__ W1,
            const float* __restrict__ W2,
            const int* __restrict__ pos,
            const int* __restrict__ neg) {
    const int bid = blockIdx.x;
    const int t   = threadIdx.x;

    if (bid < TR_BLKS) {
        __shared__ float tile[2][64][TLD];
        __shared__ unsigned char sflag[32];
        const int pt = bid % 25;
        const int b  = bid / 25;
        const int p0 = pt * 32;

        if (t < 32) sflag[t] = 0;
        __syncthreads();
#pragma unroll 4
        for (int i = t; i < MTOT; i += 256) {
            int idx = (i < M_) ? pos[i] : neg[i - M_];
            int p  = idx % HW;
            int bb = idx / (HW * A_);
            int d  = p - p0;
            if (bb == b && ((unsigned)d < 32u)) sflag[d] = 1;
        }

        const uint32_t tb0 = smem_u32(&tile[0][0][0]);
        const uint32_t tb1 = smem_u32(&tile[1][0][0]);
        const float* fb = feat + (size_t)b * CIN * HW;

        const int kk0 = t >> 3;
        const int j4  = (t & 7) * 4;
        {
#pragma unroll
            for (int h = 0; h < 2; h++) {
                int kk = kk0 + h * 32;
                int p  = p0 + j4;
                uint32_t dst = tb0 + (kk * TLD + j4) * 4;
                if (p + 3 < HW) {
                    cpa16(dst, fb + (size_t)kk * HW + p);
                } else {
                    *(float4*)((char*)&tile[0][0][0] + (kk * TLD + j4) * 4)
                        = make_float4(0.f, 0.f, 0.f, 0.f);
                }
            }
            CP_COMMIT();
        }
        __syncthreads();

        const int pr = t >> 3;
        const int gq = t & 7;
        const bool dostore = sflag[pr];

        for (int kt = 0; kt < 20; kt++) {
            if (kt + 1 < 20) {
                uint32_t tbn = (kt & 1) ? tb0 : tb1;
                float* tpn = (kt & 1) ? &tile[0][0][0] : &tile[1][0][0];
                const int k0n = (kt + 1) * 64;
#pragma unroll
                for (int h = 0; h < 2; h++) {
                    int kk = kk0 + h * 32;
                    int p  = p0 + j4;
                    if (p + 3 < HW) {
                        cpa16(tbn + (kk * TLD + j4) * 4,
                              fb + (size_t)(k0n + kk) * HW + p);
                    } else {
                        *(float4*)((char*)tpn + (kk * TLD + j4) * 4)
                            = make_float4(0.f, 0.f, 0.f, 0.f);
                    }
                }
                CP_COMMIT();
                CP_WAIT1();
            } else {
                CP_WAIT0();
            }
            __syncthreads();

            if (dostore) {
                const float (*tl)[TLD] = tile[kt & 1];
                const int k0 = kt * 64;
                size_t base = (size_t)(b * HW + p0 + pr) * CIN + k0 + gq * 8;
                uint32_t hiw[4], low[4];
#pragma unroll
                for (int i2 = 0; i2 < 4; i2++) {
                    float v0 = tl[gq * 8 + i2 * 2 + 0][pr];
                    float v1 = tl[gq * 8 + i2 * 2 + 1][pr];
                    __nv_bfloat16 h0 = __float2bfloat16(v0);
                    __nv_bfloat16 h1 = __float2bfloat16(v1);
                    hiw[i2] = PK(h0, h1);
                    low[i2] = PK(__float2bfloat16(v0 - __bfloat162float(h0)),
                                 __float2bfloat16(v1 - __bfloat162float(h1)));
                }
                *(uint4*)&g_fT_hi[base] = make_uint4(hiw[0], hiw[1], hiw[2], hiw[3]);
                *(uint4*)&g_fT_lo[base] = make_uint4(low[0], low[1], low[2], low[3]);
            }
            __syncthreads();
        }
        return;
    }

    if (bid < TR_BLKS + W1_BLKS) {
        int i4 = (bid - TR_BLKS) * 256 + t;
        const float4 v = ((const float4*)W1)[i4];
        __nv_bfloat16 h0 = __float2bfloat16(v.x), h1 = __float2bfloat16(v.y);
        __nv_bfloat16 h2 = __float2bfloat16(v.z), h3 = __float2bfloat16(v.w);
        ((uint2*)g_W1hi)[i4] = make_uint2(PK(h0, h1), PK(h2, h3));
        ((uint2*)g_W1lo)[i4] = make_uint2(
            PK(__float2bfloat16(v.x - __bfloat162float(h0)),
               __float2bfloat16(v.y - __bfloat162float(h1))),
            PK(__float2bfloat16(v.z - __bfloat162float(h2)),
               __float2bfloat16(v.w - __bfloat162float(h3))));
        return;
    }

    {
        int i4 = (bid - TR_BLKS - W1_BLKS) * 256 + t;
        if (i4 < (65 * HID) / 4) {
            const float4 v = ((const float4*)W2)[i4];
            __nv_bfloat16 h0 = __float2bfloat16(v.x), h1 = __float2bfloat16(v.y);
            __nv_bfloat16 h2 = __float2bfloat16(v.z), h3 = __float2bfloat16(v.w);
            ((uint2*)g_W2hi)[i4] = make_uint2(PK(h0, h1), PK(h2, h3));
            ((uint2*)g_W2lo)[i4] = make_uint2(
                PK(__float2bfloat16(v.x - __bfloat162float(h0)),
                   __float2bfloat16(v.y - __bfloat162float(h1))),
                PK(__float2bfloat16(v.z - __bfloat162float(h2)),
                   __float2bfloat16(v.w - __bfloat162float(h3))));
        }
    }
}

// ---------------------------------------------------------------------------
// Kernel 2: gathered WMMA GEMM (R9 config) + fused head + INTERLEAVED IoU.
//   128 blocks; block bid also owns IoU range: b_iou = bid/4, j in
//   [ (bid%4)*1764, +1764 ).  3 IoU passes (32 j x 64 n each) per k-chunk.
// ---------------------------------------------------------------------------
#define LDA 72
#define LDB 72
#define NCHUNK 20
#define SA_HI 0
#define SA_LO (64 * LDA)
#define SB_HI (2 * 64 * LDA)
#define SB_LO (2 * 64 * LDA + 128 * LDB)
#define STAGE_ELEMS (2 * 64 * LDA + 2 * 128 * LDB)   // 27648
#define NSTAGE 3
#define RING_BYTES (NSTAGE * STAGE_ELEMS * 2)        // 165888
#define IOUB_OFF   165888                             // box cache (1280 B)
#define SMEM_GEMM_BYTES (IOUB_OFF + 1280)             // 167168

#define LDS_STAGE 132
#define H_HI_OFF  34816
#define H_LO_OFF  52224
#define LDH       136
#define W2HI_OFF  69632
#define W2LO_OFF  91392
#define LDW2      136
#define ST2_OFF   113152
#define LDS2      84

#define JSEG 1764    // AHW / 4

extern __shared__ __nv_bfloat16 smem_g[];

__device__ __forceinline__ void gemm_issue(uint32_t sbase, int k0,
                                           const int* __restrict__ srow, int t) {
    {
        int row = t >> 3;
        int j   = t & 7;
        size_t src = (size_t)srow[row] * CIN + k0 + j * 8;
        cpa16(sbase + (SA_HI + row * LDA + j * 8) * 2, g_fT_hi + src);
        cpa16(sbase + (SA_LO + row * LDA + j * 8) * 2, g_fT_lo + src);
    }
#pragma unroll
    for (int h = 0; h < 2; h++) {
        int q = t + h * 512;
        int n = q >> 3;
        int j = q & 7;
        size_t src = (size_t)n * CIN + k0 + j * 8;
        cpa16(sbase + (SB_HI + n * LDB + j * 8) * 2, g_W1hi + src);
        cpa16(sbase + (SB_LO + n * LDB + j * 8) * 2, g_W1lo + src);
    }
}

__global__ void __launch_bounds__(512, 1)
gemm_iou_kernel(const int* __restrict__ pos,
                const int* __restrict__ neg,
                const float* __restrict__ b1,
                const float* __restrict__ b2,
                const float* __restrict__ grid,
                const float* __restrict__ anc,
                const float* __restrict__ bboxes,
                float* __restrict__ out) {
    __shared__ int srow[64];
    __shared__ int sanc[64];

    const int t   = threadIdx.x;
    const int wid = t >> 5;
    const int i0  = blockIdx.x * 64;
    const bool isneg = (i0 >= M_);

    // IoU ownership for this block
    const int b_iou = blockIdx.x >> 2;          // 0..31
    const int j0iou = (blockIdx.x & 3) * JSEG;  // segment start
    const int j1iou = j0iou + JSEG;
    const int n4    = (t & 15) * 4;
    const int jr    = t >> 4;                   // 0..31

    // IoU box cache in smem (past the cp.async ring)
    float* sx1 = (float*)((char*)smem_g + IOUB_OFF);
    float* sy1 = sx1 + 64;
    float* sx2 = sx1 + 128;
    float* sy2 = sx1 + 192;
    float* ssb = sx1 + 256;

    if (t < 64) {
        int gi  = i0 + t;
        int idx = (gi < M_) ? pos[gi] : neg[gi - M_];
        int p   = idx % HW;
        int ba  = idx / HW;
        srow[t] = (ba / A_) * HW + p;
        sanc[t] = ba % A_;

        const float* bb = bboxes + ((size_t)b_iou * 64 + t) * 5;
        float x1 = bb[0], y1 = bb[1], x2 = bb[2], y2 = bb[3];
        sx1[t] = x1; sy1[t] = y1; sx2[t] = x2; sy2[t] = y2;
        float sbv = (x2 - x1) * (y2 - y1);
        ssb[t] = (x1 < 0.0f) ? 0.0f : sbv;
    }
    __syncthreads();

    const uint32_t sb = smem_u32(smem_g);

    const int wr = wid >> 2;
    const int wc = wid & 3;

    wmma::fragment<wmma::accumulator, 16, 16, 16, float> acc[2];
#pragma unroll
    for (int nt = 0; nt < 2; nt++) wmma::fill_fragment(acc[nt], 0.0f);

    gemm_issue(sb, 0, srow, t);
    CP_COMMIT();
    gemm_issue(sb + STAGE_ELEMS * 2, 64, srow, t);
    CP_COMMIT();

    int stg = 0;
    for (int c = 0; c < NCHUNK; c++) {
        if (c + 2 < NCHUNK) {
            int s2 = stg + 2; if (s2 >= NSTAGE) s2 -= NSTAGE;
            gemm_issue(sb + s2 * STAGE_ELEMS * 2, (c + 2) * 64, srow, t);
            CP_COMMIT();
            CP_WAIT2();
        } else if (c + 1 < NCHUNK) {
            CP_WAIT1();
        } else {
            CP_WAIT0();
        }
        __syncthreads();

        const __nv_bfloat16* buf = smem_g + stg * STAGE_ELEMS;
#pragma unroll
        for (int ks = 0; ks < 4; ks++) {
            wmma::fragment<wmma::matrix_a, 16, 16, 16, __nv_bfloat16, wmma::row_major> a_hi, a_lo;
            wmma::load_matrix_sync(a_hi, buf + SA_HI + (wr * 16) * LDA + ks * 16, LDA);
            wmma::load_matrix_sync(a_lo, buf + SA_LO + (wr * 16) * LDA + ks * 16, LDA);
#pragma unroll
            for (int nt = 0; nt < 2; nt++) {
                int n = wc * 32 + nt * 16;
                wmma::fragment<wmma::matrix_b, 16, 16, 16, __nv_bfloat16, wmma::col_major> b_hi, b_lo;
                wmma::load_matrix_sync(b_hi, buf + SB_HI + n * LDB + ks * 16, LDB);
                wmma::load_matrix_sync(b_lo, buf + SB_LO + n * LDB + ks * 16, LDB);
                wmma::mma_sync(acc[nt], a_hi, b_hi, acc[nt]);
                wmma::mma_sync(acc[nt], a_hi, b_lo, acc[nt]);
                wmma::mma_sync(acc[nt], a_lo, b_hi, acc[nt]);
            }
        }
        __syncthreads();
        if (++stg == NSTAGE) stg = 0;

        // ---- interleaved IoU: 3 passes of 32 j x 64 n ----
#pragma unroll
        for (int ip = 0; ip < 3; ip++) {
            int j = j0iou + (c * 3 + ip) * 32 + jr;
            if (j < j1iou) {
                int a  = j / HW;
                int rr = j - a * HW;
                int h  = rr / WW;
                int w  = rr - h * WW;
                float cx = __ldg(&grid[(((size_t)b_iou * HH + h) * WW + w) * 2 + 0]);
                float cy = __ldg(&grid[(((size_t)b_iou * HH + h) * WW + w) * 2 + 1]);
                float hw2 = __ldg(&anc[a * 2 + 0]) * 0.5f;
                float hh2 = __ldg(&anc[a * 2 + 1]) * 0.5f;
                float px1 = cx - hw2, py1 = cy - hh2, px2 = cx + hw2, py2 = cy + hh2;
                float sp  = (px2 - px1) * (py2 - py1);

                float4 v;
                float* vp = &v.x;
#pragma unroll
                for (int i = 0; i < 4; i++) {
                    float qx1 = sx1[n4 + i], qy1 = sy1[n4 + i];
                    float qx2 = sx2[n4 + i], qy2 = sy2[n4 + i];
                    float qsb = ssb[n4 + i];
                    float ix1 = fmaxf(px1, qx1);
                    float iy1 = fmaxf(py1, qy1);
                    float ix2 = fminf(px2, qx2);
                    float iy2 = fminf(py2, qy2);
                    float si  = fmaxf(ix2 - ix1, 0.0f) * fmaxf(iy2 - iy1, 0.0f);
                    float su  = sp + qsb - si;
                    vp[i] = (su <= 0.0f || sp <= 0.0f || qsb <= 0.0f)
                            ? 0.0f : fmaxf(si / (su + 1e-8f), 0.0f);
                }
                *(float4*)&out[OFF_IOU + ((size_t)b_iou * AHW + j) * 64 + n4] = v;
            }
        }
    }

    // epilogue 1: accum -> stage (fp32)
    float* stage = (float*)smem_g;
#pragma unroll
    for (int nt = 0; nt < 2; nt++) {
        wmma::store_matrix_sync(&stage[(wr * 16) * LDS_STAGE + wc * 32 + nt * 16],
                                acc[nt], LDS_STAGE, wmma::mem_row_major);
    }
    __syncthreads();

    // epilogue 2: h -> bf16 hi/lo; W2 -> smem
    __nv_bfloat16* hhi  = (__nv_bfloat16*)((char*)smem_g + H_HI_OFF);
    __nv_bfloat16* hlo  = (__nv_bfloat16*)((char*)smem_g + H_LO_OFF);
    __nv_bfloat16* w2hi = (__nv_bfloat16*)((char*)smem_g + W2HI_OFF);
    __nv_bfloat16* w2lo = (__nv_bfloat16*)((char*)smem_g + W2LO_OFF);

    for (int i = t; i < 64 * 32; i += 512) {
        int row = i >> 5;
        int c4  = (i & 31) * 4;
        float4 v = *(float4*)&stage[row * LDS_STAGE + c4];
        v.x += b1[c4 + 0]; v.y += b1[c4 + 1]; v.z += b1[c4 + 2]; v.w += b1[c4 + 3];
        v.x = (v.x > 0.f) ? v.x : 0.01f * v.x;
        v.y = (v.y > 0.f) ? v.y : 0.01f * v.y;
        v.z = (v.z > 0.f) ? v.z : 0.01f * v.z;
        v.w = (v.w > 0.f) ? v.w : 0.01f * v.w;
        __nv_bfloat16 h0 = __float2bfloat16(v.x), h1 = __float2bfloat16(v.y);
        __nv_bfloat16 h2 = __float2bfloat16(v.z), h3 = __float2bfloat16(v.w);
        *(uint2*)&hhi[row * LDH + c4] = make_uint2(PK(h0, h1), PK(h2, h3));
        *(uint2*)&hlo[row * LDH + c4] = make_uint2(
            PK(__float2bfloat16(v.x - __bfloat162float(h0)),
               __float2bfloat16(v.y - __bfloat162float(h1))),
            PK(__float2bfloat16(v.z - __bfloat162float(h2)),
               __float2bfloat16(v.w - __bfloat162float(h3))));
    }
    for (int q = t; q < 80 * 16; q += 512) {
        int n = q >> 4;
        int j = q & 15;
        *(uint4*)&w2hi[n * LDW2 + j * 8] = *(const uint4*)&g_W2hi[n * HID + j * 8];
        *(uint4*)&w2lo[n * LDW2 + j * 8] = *(const uint4*)&g_W2lo[n * HID + j * 8];
    }
    __syncthreads();

    // epilogue 3: D2[64 x 80] = H @ W2^T
    float* stage2 = (float*)((char*)smem_g + ST2_OFF);
    const int ntile = isneg ? 12 : 20;
    for (int tid = wid; tid < ntile; tid += 16) {
        int wr2 = tid & 3;
        int wc2 = tid >> 2;
        wmma::fragment<wmma::accumulator, 16, 16, 16, float> acc2;
        wmma::fill_fragment(acc2, 0.0f);
#pragma unroll
        for (int ks = 0; ks < 8; ks++) {
            wmma::fragment<wmma::matrix_a, 16, 16, 16, __nv_bfloat16, wmma::row_major> a_hi, a_lo;
            wmma::load_matrix_sync(a_hi, &hhi[(wr2 * 16) * LDH + ks * 16], LDH);
            wmma::load_matrix_sync(a_lo, &hlo[(wr2 * 16) * LDH + ks * 16], LDH);
            wmma::fragment<wmma::matrix_b, 16, 16, 16, __nv_bfloat16, wmma::col_major> b_hi, b_lo;
            wmma::load_matrix_sync(b_hi, &w2hi[(wc2 * 16) * LDW2 + ks * 16], LDW2);
            wmma::load_matrix_sync(b_lo, &w2lo[(wc2 * 16) * LDW2 + ks * 16], LDW2);
            wmma::mma_sync(acc2, a_hi, b_hi, acc2);
            wmma::mma_sync(acc2, a_hi, b_lo, acc2);
            wmma::mma_sync(acc2, a_lo, b_hi, acc2);
        }
        wmma::store_matrix_sync(&stage2[(wr2 * 16) * LDS2 + wc2 * 16],
                                acc2, LDS2, wmma::mem_row_major);
    }
    __syncthreads();

    // epilogue 4: output mapping
    if (!isneg) {
        for (int e = t; e < 64 * 25; e += 512) {
            int row = e / 25;
            int q   = e - row * 25;
            int gi  = i0 + row;
            int a   = sanc[row];
            if (q == 0) {
                int n = 5 * a;
                float s = stage2[row * LDS2 + n] + b2[n];
                out[OFF_CONF + gi] = sigmoidf_(s);
            } else if (q <= 4) {
                int n = 5 * a + q;
                float s = stage2[row * LDS2 + n] + b2[n];
                out[OFF_OFFS + gi * 4 + (q - 1)] = (q <= 2) ? (sigmoidf_(s) - 0.5f) : s;
            } else {
                int n = 40 + q;
                float s = stage2[row * LDS2 + n] + b2[n];
                out[OFF_CLASS + gi * 20 + (q - 5)] = s;
            }
        }
    } else {
        if (t < 64) {
            int gi = i0 + t;
            int n  = 5 * sanc[t];
            float s = stage2[t * LDS2 + n] + b2[n];
            out[OFF_CONF + gi] = sigmoidf_(s);
        }
    }
}

// ---------------------------------------------------------------------------
// Launch
// ---------------------------------------------------------------------------
extern "C" void kernel_launch(void* const* d_in, const int* in_sizes, int n_in,
                              void* d_out, int out_size) {
    const float* features = (const float*)d_in[0];
    const float* grid     = (const float*)d_in[1];
    const float* anc      = (const float*)d_in[2];
    const float* bboxes   = (const float*)d_in[3];
    const int*   pos      = (const int*)d_in[4];
    const int*   neg      = (const int*)d_in[5];
    const float* W1       = (const float*)d_in[6];
    const float* b1       = (const float*)d_in[7];
    const float* W2       = (const float*)d_in[8];
    const float* b2       = (const float*)d_in[9];
    float* out = (float*)d_out;

    prep_kernel<<<PREP_BLKS, 256>>>(features, W1, W2, pos, neg);

    cudaFuncSetAttribute(gemm_iou_kernel,
                         cudaFuncAttributeMaxDynamicSharedMemorySize,
                         SMEM_GEMM_BYTES);
    gemm_iou_kernel<<<MTOT / 64, 512, SMEM_GEMM_BYTES>>>(
        pos, neg, b1, b2, grid, anc, bboxes, out);
}

// round 15
// speedup vs baseline: 1.3568x; 1.3568x over previous
#include <cuda_runtime.h>
#include <cuda_bf16.h>
#include <mma.h>
#include <math.h>
#include <stdint.h>

using namespace nvcuda;

// ---------------- problem constants ----------------
#define B_    32
#define CIN   1280
#define HH    28
#define WW    28
#define HW    784
#define A_    9
#define HID   128
#define M_    4096
#define MTOT  8192
#define AHW   7056
#define NPOS  (B_ * HW)        // 25088

// output layout
#define OFF_CONF   0
#define OFF_OFFS   8192
#define OFF_CLASS  24576
#define OFF_IOU    106496

// ---------------- scratch ----------------
__device__ __nv_bfloat16 g_fT_hi[(size_t)NPOS * CIN];   // [b*HW+p][k]
__device__ __nv_bfloat16 g_fT_lo[(size_t)NPOS * CIN];
__device__ __nv_bfloat16 g_W1hi[HID * CIN];             // [n][k]
__device__ __nv_bfloat16 g_W1lo[HID * CIN];
__device__ __nv_bfloat16 g_W2hi[80 * HID];              // rows 65..79 stay zero
__device__ __nv_bfloat16 g_W2lo[80 * HID];

// ---------------- helpers ----------------
__device__ __forceinline__ uint32_t smem_u32(const void* p) {
    uint32_t a;
    asm("{ .reg .u64 t; cvta.to.shared.u64 t, %1; cvt.u32.u64 %0, t; }"
        : "=r"(a) : "l"(p));
    return a;
}
__device__ __forceinline__ uint32_t PK(__nv_bfloat16 a, __nv_bfloat16 b) {
    unsigned short ua = *(unsigned short*)&a;
    unsigned short ub = *(unsigned short*)&b;
    return (uint32_t)ua | ((uint32_t)ub << 16);
}
__device__ __forceinline__ void cpa16(uint32_t dst, const void* src) {
    asm volatile("cp.async.ca.shared.global [%0], [%1], 16;" :: "r"(dst), "l"(src));
}
#define CP_COMMIT() asm volatile("cp.async.commit_group;" ::: "memory")
#define CP_WAIT0()  asm volatile("cp.async.wait_group 0;" ::: "memory")
#define CP_WAIT1()  asm volatile("cp.async.wait_group 1;" ::: "memory")
#define CP_WAIT2()  asm volatile("cp.async.wait_group 2;" ::: "memory")
#define CP_WAIT3()  asm volatile("cp.async.wait_group 3;" ::: "memory")

__device__ __forceinline__ float sigmoidf_(float x) {
    return 1.0f / (1.0f + expf(-x));
}

// ---------------------------------------------------------------------------
// Kernel 1: fused prep (R9 structure; IoU branch gets per-j smem precompute)
// ---------------------------------------------------------------------------
#define TR_BLKS  (25 * 32)          // 800
#define IOU_BLKS (56 * 32)          // 1792
#define W1_BLKS  160
#define W2_BLKS  9
#define PREP_BLKS (TR_BLKS + IOU_BLKS + W1_BLKS + W2_BLKS)

#define TLD 36                       // tile row stride (floats), 16B-aligned

__global__ void __launch_bounds__(256)
prep_kernel(const float* __restrict__ feat,
            const float* __restrict__ W1,
            const float* __restrict__ W2,
            const float* __restrict__ grid,
            const float* __restrict__ anc,
            const float* __restrict__ bboxes,
            const int* __restrict__ pos,
            const int* __restrict__ neg,
            float* __restrict__ out) {
    const int bid = blockIdx.x;
    const int t   = threadIdx.x;

    if (bid < TR_BLKS) {
        // ---- transpose + bf16 split (R9 verbatim) ----
        __shared__ float tile[2][64][TLD];
        __shared__ unsigned char sflag[32];
        const int pt = bid % 25;
        const int b  = bid / 25;
        const int p0 = pt * 32;

        if (t < 32) sflag[t] = 0;
        __syncthreads();
#pragma unroll 4
        for (int i = t; i < MTOT; i += 256) {
            int idx = (i < M_) ? pos[i] : neg[i - M_];
            int p  = idx % HW;
            int bb = idx / (HW * A_);
            int d  = p - p0;
            if (bb == b && ((unsigned)d < 32u)) sflag[d] = 1;
        }

        const uint32_t tb0 = smem_u32(&tile[0][0][0]);
        const uint32_t tb1 = smem_u32(&tile[1][0][0]);
        const float* fb = feat + (size_t)b * CIN * HW;

        const int kk0 = t >> 3;
        const int j4  = (t & 7) * 4;
        {
#pragma unroll
            for (int h = 0; h < 2; h++) {
                int kk = kk0 + h * 32;
                int p  = p0 + j4;
                uint32_t dst = tb0 + (kk * TLD + j4) * 4;
                if (p + 3 < HW) {
                    cpa16(dst, fb + (size_t)kk * HW + p);
                } else {
                    *(float4*)((char*)&tile[0][0][0] + (kk * TLD + j4) * 4)
                        = make_float4(0.f, 0.f, 0.f, 0.f);
                }
            }
            CP_COMMIT();
        }
        __syncthreads();

        const int pr = t >> 3;
        const int gq = t & 7;
        const bool dostore = sflag[pr];

        for (int kt = 0; kt < 20; kt++) {
            if (kt + 1 < 20) {
                uint32_t tbn = (kt & 1) ? tb0 : tb1;
                float* tpn = (kt & 1) ? &tile[0][0][0] : &tile[1][0][0];
                const int k0n = (kt + 1) * 64;
#pragma unroll
                for (int h = 0; h < 2; h++) {
                    int kk = kk0 + h * 32;
                    int p  = p0 + j4;
                    if (p + 3 < HW) {
                        cpa16(tbn + (kk * TLD + j4) * 4,
                              fb + (size_t)(k0n + kk) * HW + p);
                    } else {
                        *(float4*)((char*)tpn + (kk * TLD + j4) * 4)
                            = make_float4(0.f, 0.f, 0.f, 0.f);
                    }
                }
                CP_COMMIT();
                CP_WAIT1();
            } else {
                CP_WAIT0();
            }
            __syncthreads();

            if (dostore) {
                const float (*tl)[TLD] = tile[kt & 1];
                const int k0 = kt * 64;
                size_t base = (size_t)(b * HW + p0 + pr) * CIN + k0 + gq * 8;
                uint32_t hiw[4], low[4];
#pragma unroll
                for (int i2 = 0; i2 < 4; i2++) {
                    float v0 = tl[gq * 8 + i2 * 2 + 0][pr];
                    float v1 = tl[gq * 8 + i2 * 2 + 1][pr];
                    __nv_bfloat16 h0 = __float2bfloat16(v0);
                    __nv_bfloat16 h1 = __float2bfloat16(v1);
                    hiw[i2] = PK(h0, h1);
                    low[i2] = PK(__float2bfloat16(v0 - __bfloat162float(h0)),
                                 __float2bfloat16(v1 - __bfloat162float(h1)));
                }
                *(uint4*)&g_fT_hi[base] = make_uint4(hiw[0], hiw[1], hiw[2], hiw[3]);
                *(uint4*)&g_fT_lo[base] = make_uint4(low[0], low[1], low[2], low[3]);
            }
            __syncthreads();
        }
        return;
    }

    if (bid < TR_BLKS + IOU_BLKS) {
        // ---- IoU: phase A computes per-j boxes once; phase B streams n ----
        __shared__ float s_x1[64], s_y1[64], s_x2[64], s_y2[64], s_sb[64];
        __shared__ float j_x1[128], j_y1[128], j_x2[128], j_y2[128], j_sp[128];
        int r  = bid - TR_BLKS;
        int bx = r % 56;
        int b  = r / 56;
        const int j0 = bx * 128;

        if (t < 64) {
            const float* bb = bboxes + ((size_t)b * 64 + t) * 5;
            float x1 = bb[0], y1 = bb[1], x2 = bb[2], y2 = bb[3];
            s_x1[t] = x1; s_y1[t] = y1; s_x2[t] = x2; s_y2[t] = y2;
            float sb = (x2 - x1) * (y2 - y1);
            s_sb[t] = (x1 < 0.0f) ? 0.0f : sb;
        }
        if (t < 128) {
            int j = j0 + t;
            if (j < AHW) {
                int a  = j / HW;
                int rr = j - a * HW;
                int h  = rr / WW;
                int w  = rr - h * WW;
                float cx = grid[(((size_t)b * HH + h) * WW + w) * 2 + 0];
                float cy = grid[(((size_t)b * HH + h) * WW + w) * 2 + 1];
                float hw2 = anc[a * 2 + 0] * 0.5f;
                float hh2 = anc[a * 2 + 1] * 0.5f;
                j_x1[t] = cx - hw2; j_y1[t] = cy - hh2;
                j_x2[t] = cx + hw2; j_y2[t] = cy + hh2;
                j_sp[t] = (hw2 * 2.0f) * (hh2 * 2.0f);
            }
        }
        __syncthreads();

        const int n4   = (t & 15) * 4;
        const int jrow = t >> 4;          // 0..15

        float bx1[4], by1[4], bx2[4], by2[4], sb4[4];
#pragma unroll
        for (int i = 0; i < 4; i++) {
            bx1[i] = s_x1[n4 + i]; by1[i] = s_y1[n4 + i];
            bx2[i] = s_x2[n4 + i]; by2[i] = s_y2[n4 + i];
            sb4[i] = s_sb[n4 + i];
        }

#pragma unroll
        for (int it = 0; it < 8; it++) {
            int sj = it * 16 + jrow;
            int j  = j0 + sj;
            if (j >= AHW) break;
            float px1 = j_x1[sj], py1 = j_y1[sj];
            float px2 = j_x2[sj], py2 = j_y2[sj];
            float sp  = j_sp[sj];

            float4 v;
            float* vp = &v.x;
#pragma unroll
            for (int i = 0; i < 4; i++) {
                float ix1 = fmaxf(px1, bx1[i]);
                float iy1 = fmaxf(py1, by1[i]);
                float ix2 = fminf(px2, bx2[i]);
                float iy2 = fminf(py2, by2[i]);
                float si  = fmaxf(ix2 - ix1, 0.0f) * fmaxf(iy2 - iy1, 0.0f);
                float su  = sp + sb4[i] - si;
                vp[i] = (su <= 0.0f || sp <= 0.0f || sb4[i] <= 0.0f)
                        ? 0.0f : fmaxf(si / (su + 1e-8f), 0.0f);
            }
            *(float4*)&out[OFF_IOU + ((size_t)b * AHW + j) * 64 + n4] = v;
        }
        return;
    }

    if (bid < TR_BLKS + IOU_BLKS + W1_BLKS) {
        int i4 = (bid - TR_BLKS - IOU_BLKS) * 256 + t;
        const float4 v = ((const float4*)W1)[i4];
        __nv_bfloat16 h0 = __float2bfloat16(v.x), h1 = __float2bfloat16(v.y);
        __nv_bfloat16 h2 = __float2bfloat16(v.z), h3 = __float2bfloat16(v.w);
        ((uint2*)g_W1hi)[i4] = make_uint2(PK(h0, h1), PK(h2, h3));
        ((uint2*)g_W1lo)[i4] = make_uint2(
            PK(__float2bfloat16(v.x - __bfloat162float(h0)),
               __float2bfloat16(v.y - __bfloat162float(h1))),
            PK(__float2bfloat16(v.z - __bfloat162float(h2)),
               __float2bfloat16(v.w - __bfloat162float(h3))));
        return;
    }

    {
        int i4 = (bid - TR_BLKS - IOU_BLKS - W1_BLKS) * 256 + t;
        if (i4 < (65 * HID) / 4) {
            const float4 v = ((const float4*)W2)[i4];
            __nv_bfloat16 h0 = __float2bfloat16(v.x), h1 = __float2bfloat16(v.y);
            __nv_bfloat16 h2 = __float2bfloat16(v.z), h3 = __float2bfloat16(v.w);
            ((uint2*)g_W2hi)[i4] = make_uint2(PK(h0, h1), PK(h2, h3));
            ((uint2*)g_W2lo)[i4] = make_uint2(
                PK(__float2bfloat16(v.x - __bfloat162float(h0)),
                   __float2bfloat16(v.y - __bfloat162float(h1))),
                PK(__float2bfloat16(v.z - __bfloat162float(h2)),
                   __float2bfloat16(v.w - __bfloat162float(h3))));
        }
    }
}

// ---------------------------------------------------------------------------
// Kernel 2: gathered WMMA GEMM + fused head epilogue.
//   R9 config, pipeline deepened: 4-stage cp.async ring, prefetch distance 3,
//   SAME 2-barrier chunk body.
// ---------------------------------------------------------------------------
#define LDA 72
#define LDB 72
#define NCHUNK 20
#define SA_HI 0
#define SA_LO (64 * LDA)
#define SB_HI (2 * 64 * LDA)
#define SB_LO (2 * 64 * LDA + 128 * LDB)
#define STAGE_ELEMS (2 * 64 * LDA + 2 * 128 * LDB)   // 27648
#define NSTAGE 4
#define SMEM_GEMM_BYTES (NSTAGE * STAGE_ELEMS * 2)   // 221184

#define LDS_STAGE 132
#define H_HI_OFF  34816
#define H_LO_OFF  52224
#define LDH       136
#define W2HI_OFF  69632
#define W2LO_OFF  91392
#define LDW2      136
#define ST2_OFF   113152
#define LDS2      84

extern __shared__ __nv_bfloat16 smem_g[];

__device__ __forceinline__ void gemm_issue(uint32_t sbase, int k0,
                                           const int* __restrict__ srow, int t) {
    {
        int row = t >> 3;
        int j   = t & 7;
        size_t src = (size_t)srow[row] * CIN + k0 + j * 8;
        cpa16(sbase + (SA_HI + row * LDA + j * 8) * 2, g_fT_hi + src);
        cpa16(sbase + (SA_LO + row * LDA + j * 8) * 2, g_fT_lo + src);
    }
#pragma unroll
    for (int h = 0; h < 2; h++) {
        int q = t + h * 512;
        int n = q >> 3;
        int j = q & 7;
        size_t src = (size_t)n * CIN + k0 + j * 8;
        cpa16(sbase + (SB_HI + n * LDB + j * 8) * 2, g_W1hi + src);
        cpa16(sbase + (SB_LO + n * LDB + j * 8) * 2, g_W1lo + src);
    }
}

__global__ void __launch_bounds__(512, 1)
gemm_wmma_kernel(const int* __restrict__ pos,
                 const int* __restrict__ neg,
                 const float* __restrict__ b1,
                 const float* __restrict__ b2,
                 float* __restrict__ out) {
    __shared__ int srow[64];
    __shared__ int sanc[64];

    const int t   = threadIdx.x;
    const int wid = t >> 5;
    const int i0  = blockIdx.x * 64;
    const bool isneg = (i0 >= M_);

    if (t < 64) {
        int gi  = i0 + t;
        int idx = (gi < M_) ? pos[gi] : neg[gi - M_];
        int p   = idx % HW;
        int ba  = idx / HW;
        srow[t] = (ba / A_) * HW + p;
        sanc[t] = ba % A_;
    }
    __syncthreads();

    const uint32_t sb = smem_u32(smem_g);

    const int wr = wid >> 2;
    const int wc = wid & 3;

    wmma::fragment<wmma::accumulator, 16, 16, 16, float> acc[2];
#pragma unroll
    for (int nt = 0; nt < 2; nt++) wmma::fill_fragment(acc[nt], 0.0f);

    // prologue: 3 chunks in flight (distance 3, 4-stage ring)
    gemm_issue(sb, 0, srow, t);
    CP_COMMIT();
    gemm_issue(sb + 1 * STAGE_ELEMS * 2, 64, srow, t);
    CP_COMMIT();
    gemm_issue(sb + 2 * STAGE_ELEMS * 2, 128, srow, t);
    CP_COMMIT();

    int stg = 0;
    for (int c = 0; c < NCHUNK; c++) {
        if (c + 3 < NCHUNK) {
            int s3 = stg + 3; if (s3 >= NSTAGE) s3 -= NSTAGE;
            gemm_issue(sb + s3 * STAGE_ELEMS * 2, (c + 3) * 64, srow, t);
            CP_COMMIT();
            CP_WAIT3();
        } else if (c + 2 < NCHUNK) {
            CP_WAIT2();
        } else if (c + 1 < NCHUNK) {
            CP_WAIT1();
        } else {
            CP_WAIT0();
        }
        __syncthreads();

        const __nv_bfloat16* buf = smem_g + stg * STAGE_ELEMS;
#pragma unroll
        for (int ks = 0; ks < 4; ks++) {
            wmma::fragment<wmma::matrix_a, 16, 16, 16, __nv_bfloat16, wmma::row_major> a_hi, a_lo;
            wmma::load_matrix_sync(a_hi, buf + SA_HI + (wr * 16) * LDA + ks * 16, LDA);
            wmma::load_matrix_sync(a_lo, buf + SA_LO + (wr * 16) * LDA + ks * 16, LDA);
#pragma unroll
            for (int nt = 0; nt < 2; nt++) {
                int n = wc * 32 + nt * 16;
                wmma::fragment<wmma::matrix_b, 16, 16, 16, __nv_bfloat16, wmma::col_major> b_hi, b_lo;
                wmma::load_matrix_sync(b_hi, buf + SB_HI + n * LDB + ks * 16, LDB);
                wmma::load_matrix_sync(b_lo, buf + SB_LO + n * LDB + ks * 16, LDB);
                wmma::mma_sync(acc[nt], a_hi, b_hi, acc[nt]);
                wmma::mma_sync(acc[nt], a_hi, b_lo, acc[nt]);
                wmma::mma_sync(acc[nt], a_lo, b_hi, acc[nt]);
            }
        }
        __syncthreads();
        if (++stg == NSTAGE) stg = 0;
    }

    // epilogue 1: accum -> stage (fp32)
    float* stage = (float*)smem_g;
#pragma unroll
    for (int nt = 0; nt < 2; nt++) {
        wmma::store_matrix_sync(&stage[(wr * 16) * LDS_STAGE + wc * 32 + nt * 16],
                                acc[nt], LDS_STAGE, wmma::mem_row_major);
    }
    __syncthreads();

    // epilogue 2: h -> bf16 hi/lo; W2 -> smem
    __nv_bfloat16* hhi  = (__nv_bfloat16*)((char*)smem_g + H_HI_OFF);
    __nv_bfloat16* hlo  = (__nv_bfloat16*)((char*)smem_g + H_LO_OFF);
    __nv_bfloat16* w2hi = (__nv_bfloat16*)((char*)smem_g + W2HI_OFF);
    __nv_bfloat16* w2lo = (__nv_bfloat16*)((char*)smem_g + W2LO_OFF);

    for (int i = t; i < 64 * 32; i += 512) {
        int row = i >> 5;
        int c4  = (i & 31) * 4;
        float4 v = *(float4*)&stage[row * LDS_STAGE + c4];
        v.x += b1[c4 + 0]; v.y += b1[c4 + 1]; v.z += b1[c4 + 2]; v.w += b1[c4 + 3];
        v.x = (v.x > 0.f) ? v.x : 0.01f * v.x;
        v.y = (v.y > 0.f) ? v.y : 0.01f * v.y;
        v.z = (v.z > 0.f) ? v.z : 0.01f * v.z;
        v.w = (v.w > 0.f) ? v.w : 0.01f * v.w;
        __nv_bfloat16 h0 = __float2bfloat16(v.x), h1 = __float2bfloat16(v.y);
        __nv_bfloat16 h2 = __float2bfloat16(v.z), h3 = __float2bfloat16(v.w);
        *(uint2*)&hhi[row * LDH + c4] = make_uint2(PK(h0, h1), PK(h2, h3));
        *(uint2*)&hlo[row * LDH + c4] = make_uint2(
            PK(__float2bfloat16(v.x - __bfloat162float(h0)),
               __float2bfloat16(v.y - __bfloat162float(h1))),
            PK(__float2bfloat16(v.z - __bfloat162float(h2)),
               __float2bfloat16(v.w - __bfloat162float(h3))));
    }
    for (int q = t; q < 80 * 16; q += 512) {
        int n = q >> 4;
        int j = q & 15;
        *(uint4*)&w2hi[n * LDW2 + j * 8] = *(const uint4*)&g_W2hi[n * HID + j * 8];
        *(uint4*)&w2lo[n * LDW2 + j * 8] = *(const uint4*)&g_W2lo[n * HID + j * 8];
    }
    __syncthreads();

    // epilogue 3: D2[64 x 80] = H @ W2^T
    float* stage2 = (float*)((char*)smem_g + ST2_OFF);
    const int ntile = isneg ? 12 : 20;
    for (int tid = wid; tid < ntile; tid += 16) {
        int wr2 = tid & 3;
        int wc2 = tid >> 2;
        wmma::fragment<wmma::accumulator, 16, 16, 16, float> acc2;
        wmma::fill_fragment(acc2, 0.0f);
#pragma unroll
        for (int ks = 0; ks < 8; ks++) {
            wmma::fragment<wmma::matrix_a, 16, 16, 16, __nv_bfloat16, wmma::row_major> a_hi, a_lo;
            wmma::load_matrix_sync(a_hi, &hhi[(wr2 * 16) * LDH + ks * 16], LDH);
            wmma::load_matrix_sync(a_lo, &hlo[(wr2 * 16) * LDH + ks * 16], LDH);
            wmma::fragment<wmma::matrix_b, 16, 16, 16, __nv_bfloat16, wmma::col_major> b_hi, b_lo;
            wmma::load_matrix_sync(b_hi, &w2hi[(wc2 * 16) * LDW2 + ks * 16], LDW2);
            wmma::load_matrix_sync(b_lo, &w2lo[(wc2 * 16) * LDW2 + ks * 16], LDW2);
            wmma::mma_sync(acc2, a_hi, b_hi, acc2);
            wmma::mma_sync(acc2, a_hi, b_lo, acc2);
            wmma::mma_sync(acc2, a_lo, b_hi, acc2);
        }
        wmma::store_matrix_sync(&stage2[(wr2 * 16) * LDS2 + wc2 * 16],
                                acc2, LDS2, wmma::mem_row_major);
    }
    __syncthreads();

    // epilogue 4: output mapping
    if (!isneg) {
        for (int e = t; e < 64 * 25; e += 512) {
            int row = e / 25;
            int q   = e - row * 25;
            int gi  = i0 + row;
            int a   = sanc[row];
            if (q == 0) {
                int n = 5 * a;
                float s = stage2[row * LDS2 + n] + b2[n];
                out[OFF_CONF + gi] = sigmoidf_(s);
            } else if (q <= 4) {
                int n = 5 * a + q;
                float s = stage2[row * LDS2 + n] + b2[n];
                out[OFF_OFFS + gi * 4 + (q - 1)] = (q <= 2) ? (sigmoidf_(s) - 0.5f) : s;
            } else {
                int n = 40 + q;
                float s = stage2[row * LDS2 + n] + b2[n];
                out[OFF_CLASS + gi * 20 + (q - 5)] = s;
            }
        }
    } else {
        if (t < 64) {
            int gi = i0 + t;
            int n  = 5 * sanc[t];
            float s = stage2[t * LDS2 + n] + b2[n];
            out[OFF_CONF + gi] = sigmoidf_(s);
        }
    }
}

// ---------------------------------------------------------------------------
// Launch
// ---------------------------------------------------------------------------
extern "C" void kernel_launch(void* const* d_in, const int* in_sizes, int n_in,
                              void* d_out, int out_size) {
    const float* features = (const float*)d_in[0];
    const float* grid     = (const float*)d_in[1];
    const float* anc      = (const float*)d_in[2];
    const float* bboxes   = (const float*)d_in[3];
    const int*   pos      = (const int*)d_in[4];
    const int*   neg      = (const int*)d_in[5];
    const float* W1       = (const float*)d_in[6];
    const float* b1       = (const float*)d_in[7];
    const float* W2       = (const float*)d_in[8];
    const float* b2       = (const float*)d_in[9];
    float* out = (float*)d_out;

    prep_kernel<<<PREP_BLKS, 256>>>(features, W1, W2, grid, anc, bboxes,
                                    pos, neg, out);

    cudaFuncSetAttribute(gemm_wmma_kernel,
                         cudaFuncAttributeMaxDynamicSharedMemorySize,
                         SMEM_GEMM_BYTES);
    gemm_wmma_kernel<<<MTOT / 64, 512, SMEM_GEMM_BYTES>>>(pos, neg, b1, b2, out);
}

// round 16
// speedup vs baseline: 1.4685x; 1.0823x over previous
#include <cuda_runtime.h>
#include <cuda_bf16.h>
#include <mma.h>
#include <math.h>
#include <stdint.h>

using namespace nvcuda;

// ---------------- problem constants ----------------
#define B_    32
#define CIN   1280
#define HH    28
#define WW    28
#define HW    784
#define A_    9
#define HID   128
#define M_    4096
#define MTOT  8192
#define AHW   7056
#define NPOS  (B_ * HW)        // 25088

// output layout
#define OFF_CONF   0
#define OFF_OFFS   8192
#define OFF_CLASS  24576
#define OFF_IOU    106496

// ---------------- scratch ----------------
__device__ __nv_bfloat16 g_fT_hi[(size_t)NPOS * CIN];   // [b*HW+p][k]
__device__ __nv_bfloat16 g_fT_lo[(size_t)NPOS * CIN];
__device__ __nv_bfloat16 g_W1hi[HID * CIN];             // [n][k]
__device__ __nv_bfloat16 g_W1lo[HID * CIN];
__device__ __nv_bfloat16 g_W2hi[80 * HID];              // rows 65..79 stay zero
__device__ __nv_bfloat16 g_W2lo[80 * HID];

// ---------------- helpers ----------------
__device__ __forceinline__ uint32_t smem_u32(const void* p) {
    uint32_t a;
    asm("{ .reg .u64 t; cvta.to.shared.u64 t, %1; cvt.u32.u64 %0, t; }"
        : "=r"(a) : "l"(p));
    return a;
}
__device__ __forceinline__ uint32_t PK(__nv_bfloat16 a, __nv_bfloat16 b) {
    unsigned short ua = *(unsigned short*)&a;
    unsigned short ub = *(unsigned short*)&b;
    return (uint32_t)ua | ((uint32_t)ub << 16);
}
__device__ __forceinline__ void cpa16(uint32_t dst, const void* src) {
    asm volatile("cp.async.ca.shared.global [%0], [%1], 16;" :: "r"(dst), "l"(src));
}
#define CP_COMMIT() asm volatile("cp.async.commit_group;" ::: "memory")
#define CP_WAIT0()  asm volatile("cp.async.wait_group 0;" ::: "memory")
#define CP_WAIT1()  asm volatile("cp.async.wait_group 1;" ::: "memory")
#define CP_WAIT2()  asm volatile("cp.async.wait_group 2;" ::: "memory")

__device__ __forceinline__ float sigmoidf_(float x) {
    return 1.0f / (1.0f + expf(-x));
}

// ---------------------------------------------------------------------------
// Kernel 1: fused prep.
//   transpose: 3-buffer cp.async ring, prefetch distance 2 (deeper MLP),
//              2 barriers per iter (proven-safe body)
//   IoU: phase-A per-j box precompute (R15), phase-B n-stream
//   + W1/W2 splits
// ---------------------------------------------------------------------------
#define TR_BLKS  (25 * 32)          // 800
#define IOU_BLKS (56 * 32)          // 1792
#define W1_BLKS  160
#define W2_BLKS  9
#define PREP_BLKS (TR_BLKS + IOU_BLKS + W1_BLKS + W2_BLKS)

#define TLD 36                       // tile row stride (floats), 16B-aligned

__global__ void __launch_bounds__(256)
prep_kernel(const float* __restrict__ feat,
            const float* __restrict__ W1,
            const float* __restrict__ W2,
            const float* __restrict__ grid,
            const float* __restrict__ anc,
            const float* __restrict__ bboxes,
            const int* __restrict__ pos,
            const int* __restrict__ neg,
            float* __restrict__ out) {
    const int bid = blockIdx.x;
    const int t   = threadIdx.x;

    if (bid < TR_BLKS) {
        // ---- transpose + bf16 split (3-buffer ring, distance 2) ----
        __shared__ float tile[3][64][TLD];
        __shared__ unsigned char sflag[32];
        const int pt = bid % 25;
        const int b  = bid / 25;
        const int p0 = pt * 32;

        if (t < 32) sflag[t] = 0;
        __syncthreads();
#pragma unroll 4
        for (int i = t; i < MTOT; i += 256) {
            int idx = (i < M_) ? pos[i] : neg[i - M_];
            int p  = idx % HW;
            int bb = idx / (HW * A_);
            int d  = p - p0;
            if (bb == b && ((unsigned)d < 32u)) sflag[d] = 1;
        }

        uint32_t tb[3];
        tb[0] = smem_u32(&tile[0][0][0]);
        tb[1] = smem_u32(&tile[1][0][0]);
        tb[2] = smem_u32(&tile[2][0][0]);
        const float* fb = feat + (size_t)b * CIN * HW;

        const int kk0 = t >> 3;            // k row phase (0..31)
        const int j4  = (t & 7) * 4;       // p offset
        const int p   = p0 + j4;
        const bool inb = (p + 3 < HW);

        // prologue: issue kt=0 (buf0), kt=1 (buf1)
#pragma unroll
        for (int pre = 0; pre < 2; pre++) {
#pragma unroll
            for (int h = 0; h < 2; h++) {
                int kk = kk0 + h * 32;
                if (inb) cpa16(tb[pre] + (kk * TLD + j4) * 4,
                               fb + (size_t)(pre * 64 + kk) * HW + p);
                else *(float4*)((char*)&tile[pre][0][0] + (kk * TLD + j4) * 4)
                        = make_float4(0.f, 0.f, 0.f, 0.f);
            }
            CP_COMMIT();
        }
        __syncthreads();   // flags visible

        const int pr = t >> 3;
        const int gq = t & 7;
        const bool dostore = sflag[pr];

        for (int kt = 0; kt < 20; kt++) {
            const int buf = kt % 3;
            if (kt + 2 < 20) {
                int bn = (kt + 2) % 3;
                const int k0n = (kt + 2) * 64;
#pragma unroll
                for (int h = 0; h < 2; h++) {
                    int kk = kk0 + h * 32;
                    if (inb) cpa16(tb[bn] + (kk * TLD + j4) * 4,
                                   fb + (size_t)(k0n + kk) * HW + p);
                    else *(float4*)((char*)&tile[bn][0][0] + (kk * TLD + j4) * 4)
                            = make_float4(0.f, 0.f, 0.f, 0.f);
                }
                CP_COMMIT();
                CP_WAIT2();
            } else if (kt + 1 < 20) {
                CP_WAIT1();
            } else {
                CP_WAIT0();
            }
            __syncthreads();

            if (dostore) {
                const float (*tl)[TLD] = tile[buf];
                const int k0 = kt * 64;
                size_t base = (size_t)(b * HW + p0 + pr) * CIN + k0 + gq * 8;
                uint32_t hiw[4], low[4];
#pragma unroll
                for (int i2 = 0; i2 < 4; i2++) {
                    float v0 = tl[gq * 8 + i2 * 2 + 0][pr];
                    float v1 = tl[gq * 8 + i2 * 2 + 1][pr];
                    __nv_bfloat16 h0 = __float2bfloat16(v0);
                    __nv_bfloat16 h1 = __float2bfloat16(v1);
                    hiw[i2] = PK(h0, h1);
                    low[i2] = PK(__float2bfloat16(v0 - __bfloat162float(h0)),
                                 __float2bfloat16(v1 - __bfloat162float(h1)));
                }
                *(uint4*)&g_fT_hi[base] = make_uint4(hiw[0], hiw[1], hiw[2], hiw[3]);
                *(uint4*)&g_fT_lo[base] = make_uint4(low[0], low[1], low[2], low[3]);
            }
            __syncthreads();
        }
        return;
    }

    if (bid < TR_BLKS + IOU_BLKS) {
        // ---- IoU: phase A computes per-j boxes once; phase B streams n ----
        __shared__ float s_x1[64], s_y1[64], s_x2[64], s_y2[64], s_sb[64];
        __shared__ float j_x1[128], j_y1[128], j_x2[128], j_y2[128], j_sp[128];
        int r  = bid - TR_BLKS;
        int bx = r % 56;
        int b  = r / 56;
        const int j0 = bx * 128;

        if (t < 64) {
            const float* bb = bboxes + ((size_t)b * 64 + t) * 5;
            float x1 = bb[0], y1 = bb[1], x2 = bb[2], y2 = bb[3];
            s_x1[t] = x1; s_y1[t] = y1; s_x2[t] = x2; s_y2[t] = y2;
            float sb = (x2 - x1) * (y2 - y1);
            s_sb[t] = (x1 < 0.0f) ? 0.0f : sb;
        }
        if (t < 128) {
            int j = j0 + t;
            if (j < AHW) {
                int a  = j / HW;
                int rr = j - a * HW;
                int h  = rr / WW;
                int w  = rr - h * WW;
                float cx = grid[(((size_t)b * HH + h) * WW + w) * 2 + 0];
                float cy = grid[(((size_t)b * HH + h) * WW + w) * 2 + 1];
                float hw2 = anc[a * 2 + 0] * 0.5f;
                float hh2 = anc[a * 2 + 1] * 0.5f;
                j_x1[t] = cx - hw2; j_y1[t] = cy - hh2;
                j_x2[t] = cx + hw2; j_y2[t] = cy + hh2;
                j_sp[t] = (hw2 * 2.0f) * (hh2 * 2.0f);
            }
        }
        __syncthreads();

        const int n4   = (t & 15) * 4;
        const int jrow = t >> 4;          // 0..15

        float bx1[4], by1[4], bx2[4], by2[4], sb4[4];
#pragma unroll
        for (int i = 0; i < 4; i++) {
            bx1[i] = s_x1[n4 + i]; by1[i] = s_y1[n4 + i];
            bx2[i] = s_x2[n4 + i]; by2[i] = s_y2[n4 + i];
            sb4[i] = s_sb[n4 + i];
        }

#pragma unroll
        for (int it = 0; it < 8; it++) {
            int sj = it * 16 + jrow;
            int j  = j0 + sj;
            if (j >= AHW) break;
            float px1 = j_x1[sj], py1 = j_y1[sj];
            float px2 = j_x2[sj], py2 = j_y2[sj];
            float sp  = j_sp[sj];

            float4 v;
            float* vp = &v.x;
#pragma unroll
            for (int i = 0; i < 4; i++) {
                float ix1 = fmaxf(px1, bx1[i]);
                float iy1 = fmaxf(py1, by1[i]);
                float ix2 = fminf(px2, bx2[i]);
                float iy2 = fminf(py2, by2[i]);
                float si  = fmaxf(ix2 - ix1, 0.0f) * fmaxf(iy2 - iy1, 0.0f);
                float su  = sp + sb4[i] - si;
                vp[i] = (su <= 0.0f || sp <= 0.0f || sb4[i] <= 0.0f)
                        ? 0.0f : fmaxf(si / (su + 1e-8f), 0.0f);
            }
            *(float4*)&out[OFF_IOU + ((size_t)b * AHW + j) * 64 + n4] = v;
        }
        return;
    }

    if (bid < TR_BLKS + IOU_BLKS + W1_BLKS) {
        int i4 = (bid - TR_BLKS - IOU_BLKS) * 256 + t;
        const float4 v = ((const float4*)W1)[i4];
        __nv_bfloat16 h0 = __float2bfloat16(v.x), h1 = __float2bfloat16(v.y);
        __nv_bfloat16 h2 = __float2bfloat16(v.z), h3 = __float2bfloat16(v.w);
        ((uint2*)g_W1hi)[i4] = make_uint2(PK(h0, h1), PK(h2, h3));
        ((uint2*)g_W1lo)[i4] = make_uint2(
            PK(__float2bfloat16(v.x - __bfloat162float(h0)),
               __float2bfloat16(v.y - __bfloat162float(h1))),
            PK(__float2bfloat16(v.z - __bfloat162float(h2)),
               __float2bfloat16(v.w - __bfloat162float(h3))));
        return;
    }

    {
        int i4 = (bid - TR_BLKS - IOU_BLKS - W1_BLKS) * 256 + t;
        if (i4 < (65 * HID) / 4) {
            const float4 v = ((const float4*)W2)[i4];
            __nv_bfloat16 h0 = __float2bfloat16(v.x), h1 = __float2bfloat16(v.y);
            __nv_bfloat16 h2 = __float2bfloat16(v.z), h3 = __float2bfloat16(v.w);
            ((uint2*)g_W2hi)[i4] = make_uint2(PK(h0, h1), PK(h2, h3));
            ((uint2*)g_W2lo)[i4] = make_uint2(
                PK(__float2bfloat16(v.x - __bfloat162float(h0)),
                   __float2bfloat16(v.y - __bfloat162float(h1))),
                PK(__float2bfloat16(v.z - __bfloat162float(h2)),
                   __float2bfloat16(v.w - __bfloat162float(h3))));
        }
    }
}

// ---------------------------------------------------------------------------
// Kernel 2: gathered WMMA GEMM + fused head epilogue.
//   EXACT R9 config: 64x128 tile, 512 threads, KTILE=64, 3-stage ring,
//   prefetch distance 2, 2 barriers per chunk, 166 KB smem. DO NOT TOUCH.
// ---------------------------------------------------------------------------
#define LDA 72
#define LDB 72
#define NCHUNK 20
#define SA_HI 0
#define SA_LO (64 * LDA)
#define SB_HI (2 * 64 * LDA)
#define SB_LO (2 * 64 * LDA + 128 * LDB)
#define STAGE_ELEMS (2 * 64 * LDA + 2 * 128 * LDB)   // 27648
#define NSTAGE 3
#define SMEM_GEMM_BYTES (NSTAGE * STAGE_ELEMS * 2)   // 165888

#define LDS_STAGE 132
#define H_HI_OFF  34816
#define H_LO_OFF  52224
#define LDH       136
#define W2HI_OFF  69632
#define W2LO_OFF  91392
#define LDW2      136
#define ST2_OFF   113152
#define LDS2      84

extern __shared__ __nv_bfloat16 smem_g[];

__device__ __forceinline__ void gemm_issue(uint32_t sbase, int k0,
                                           const int* __restrict__ srow, int t) {
    {
        int row = t >> 3;
        int j   = t & 7;
        size_t src = (size_t)srow[row] * CIN + k0 + j * 8;
        cpa16(sbase + (SA_HI + row * LDA + j * 8) * 2, g_fT_hi + src);
        cpa16(sbase + (SA_LO + row * LDA + j * 8) * 2, g_fT_lo + src);
    }
#pragma unroll
    for (int h = 0; h < 2; h++) {
        int q = t + h * 512;
        int n = q >> 3;
        int j = q & 7;
        size_t src = (size_t)n * CIN + k0 + j * 8;
        cpa16(sbase + (SB_HI + n * LDB + j * 8) * 2, g_W1hi + src);
        cpa16(sbase + (SB_LO + n * LDB + j * 8) * 2, g_W1lo + src);
    }
}

__global__ void __launch_bounds__(512, 1)
gemm_wmma_kernel(const int* __restrict__ pos,
                 const int* __restrict__ neg,
                 const float* __restrict__ b1,
                 const float* __restrict__ b2,
                 float* __restrict__ out) {
    __shared__ int srow[64];
    __shared__ int sanc[64];

    const int t   = threadIdx.x;
    const int wid = t >> 5;
    const int i0  = blockIdx.x * 64;
    const bool isneg = (i0 >= M_);

    if (t < 64) {
        int gi  = i0 + t;
        int idx = (gi < M_) ? pos[gi] : neg[gi - M_];
        int p   = idx % HW;
        int ba  = idx / HW;
        srow[t] = (ba / A_) * HW + p;
        sanc[t] = ba % A_;
    }
    __syncthreads();

    const uint32_t sb = smem_u32(smem_g);

    const int wr = wid >> 2;
    const int wc = wid & 3;

    wmma::fragment<wmma::accumulator, 16, 16, 16, float> acc[2];
#pragma unroll
    for (int nt = 0; nt < 2; nt++) wmma::fill_fragment(acc[nt], 0.0f);

    gemm_issue(sb, 0, srow, t);
    CP_COMMIT();
    gemm_issue(sb + STAGE_ELEMS * 2, 64, srow, t);
    CP_COMMIT();

    int stg = 0;
    for (int c = 0; c < NCHUNK; c++) {
        if (c + 2 < NCHUNK) {
            int s2 = stg + 2; if (s2 >= NSTAGE) s2 -= NSTAGE;
            gemm_issue(sb + s2 * STAGE_ELEMS * 2, (c + 2) * 64, srow, t);
            CP_COMMIT();
            CP_WAIT2();
        } else if (c + 1 < NCHUNK) {
            CP_WAIT1();
        } else {
            CP_WAIT0();
        }
        __syncthreads();

        const __nv_bfloat16* buf = smem_g + stg * STAGE_ELEMS;
#pragma unroll
        for (int ks = 0; ks < 4; ks++) {
            wmma::fragment<wmma::matrix_a, 16, 16, 16, __nv_bfloat16, wmma::row_major> a_hi, a_lo;
            wmma::load_matrix_sync(a_hi, buf + SA_HI + (wr * 16) * LDA + ks * 16, LDA);
            wmma::load_matrix_sync(a_lo, buf + SA_LO + (wr * 16) * LDA + ks * 16, LDA);
#pragma unroll
            for (int nt = 0; nt < 2; nt++) {
                int n = wc * 32 + nt * 16;
                wmma::fragment<wmma::matrix_b, 16, 16, 16, __nv_bfloat16, wmma::col_major> b_hi, b_lo;
                wmma::load_matrix_sync(b_hi, buf + SB_HI + n * LDB + ks * 16, LDB);
                wmma::load_matrix_sync(b_lo, buf + SB_LO + n * LDB + ks * 16, LDB);
                wmma::mma_sync(acc[nt], a_hi, b_hi, acc[nt]);
                wmma::mma_sync(acc[nt], a_hi, b_lo, acc[nt]);
                wmma::mma_sync(acc[nt], a_lo, b_hi, acc[nt]);
            }
        }
        __syncthreads();
        if (++stg == NSTAGE) stg = 0;
    }

    // epilogue 1: accum -> stage (fp32)
    float* stage = (float*)smem_g;
#pragma unroll
    for (int nt = 0; nt < 2; nt++) {
        wmma::store_matrix_sync(&stage[(wr * 16) * LDS_STAGE + wc * 32 + nt * 16],
                                acc[nt], LDS_STAGE, wmma::mem_row_major);
    }
    __syncthreads();

    // epilogue 2: h -> bf16 hi/lo; W2 -> smem
    __nv_bfloat16* hhi  = (__nv_bfloat16*)((char*)smem_g + H_HI_OFF);
    __nv_bfloat16* hlo  = (__nv_bfloat16*)((char*)smem_g + H_LO_OFF);
    __nv_bfloat16* w2hi = (__nv_bfloat16*)((char*)smem_g + W2HI_OFF);
    __nv_bfloat16* w2lo = (__nv_bfloat16*)((char*)smem_g + W2LO_OFF);

    for (int i = t; i < 64 * 32; i += 512) {
        int row = i >> 5;
        int c4  = (i & 31) * 4;
        float4 v = *(float4*)&stage[row * LDS_STAGE + c4];
        v.x += b1[c4 + 0]; v.y += b1[c4 + 1]; v.z += b1[c4 + 2]; v.w += b1[c4 + 3];
        v.x = (v.x > 0.f) ? v.x : 0.01f * v.x;
        v.y = (v.y > 0.f) ? v.y : 0.01f * v.y;
        v.z = (v.z > 0.f) ? v.z : 0.01f * v.z;
        v.w = (v.w > 0.f) ? v.w : 0.01f * v.w;
        __nv_bfloat16 h0 = __float2bfloat16(v.x), h1 = __float2bfloat16(v.y);
        __nv_bfloat16 h2 = __float2bfloat16(v.z), h3 = __float2bfloat16(v.w);
        *(uint2*)&hhi[row * LDH + c4] = make_uint2(PK(h0, h1), PK(h2, h3));
        *(uint2*)&hlo[row * LDH + c4] = make_uint2(
            PK(__float2bfloat16(v.x - __bfloat162float(h0)),
               __float2bfloat16(v.y - __bfloat162float(h1))),
            PK(__float2bfloat16(v.z - __bfloat162float(h2)),
               __float2bfloat16(v.w - __bfloat162float(h3))));
    }
    for (int q = t; q < 80 * 16; q += 512) {
        int n = q >> 4;
        int j = q & 15;
        *(uint4*)&w2hi[n * LDW2 + j * 8] = *(const uint4*)&g_W2hi[n * HID + j * 8];
        *(uint4*)&w2lo[n * LDW2 + j * 8] = *(const uint4*)&g_W2lo[n * HID + j * 8];
    }
    __syncthreads();

    // epilogue 3: D2[64 x 80] = H @ W2^T
    float* stage2 = (float*)((char*)smem_g + ST2_OFF);
    const int ntile = isneg ? 12 : 20;
    for (int tid = wid; tid < ntile; tid += 16) {
        int wr2 = tid & 3;
        int wc2 = tid >> 2;
        wmma::fragment<wmma::accumulator, 16, 16, 16, float> acc2;
        wmma::fill_fragment(acc2, 0.0f);
#pragma unroll
        for (int ks = 0; ks < 8; ks++) {
            wmma::fragment<wmma::matrix_a, 16, 16, 16, __nv_bfloat16, wmma::row_major> a_hi, a_lo;
            wmma::load_matrix_sync(a_hi, &hhi[(wr2 * 16) * LDH + ks * 16], LDH);
            wmma::load_matrix_sync(a_lo, &hlo[(wr2 * 16) * LDH + ks * 16], LDH);
            wmma::fragment<wmma::matrix_b, 16, 16, 16, __nv_bfloat16, wmma::col_major> b_hi, b_lo;
            wmma::load_matrix_sync(b_hi, &w2hi[(wc2 * 16) * LDW2 + ks * 16], LDW2);
            wmma::load_matrix_sync(b_lo, &w2lo[(wc2 * 16) * LDW2 + ks * 16], LDW2);
            wmma::mma_sync(acc2, a_hi, b_hi, acc2);
            wmma::mma_sync(acc2, a_hi, b_lo, acc2);
            wmma::mma_sync(acc2, a_lo, b_hi, acc2);
        }
        wmma::store_matrix_sync(&stage2[(wr2 * 16) * LDS2 + wc2 * 16],
                                acc2, LDS2, wmma::mem_row_major);
    }
    __syncthreads();

    // epilogue 4: output mapping
    if (!isneg) {
        for (int e = t; e < 64 * 25; e += 512) {
            int row = e / 25;
            int q   = e - row * 25;
            int gi  = i0 + row;
            int a   = sanc[row];
            if (q == 0) {
                int n = 5 * a;
                float s = stage2[row * LDS2 + n] + b2[n];
                out[OFF_CONF + gi] = sigmoidf_(s);
            } else if (q <= 4) {
                int n = 5 * a + q;
                float s = stage2[row * LDS2 + n] + b2[n];
                out[OFF_OFFS + gi * 4 + (q - 1)] = (q <= 2) ? (sigmoidf_(s) - 0.5f) : s;
            } else {
                int n = 40 + q;
                float s = stage2[row * LDS2 + n] + b2[n];
                out[OFF_CLASS + gi * 20 + (q - 5)] = s;
            }
        }
    } else {
        if (t < 64) {
            int gi = i0 + t;
            int n  = 5 * sanc[t];
            float s = stage2[t * LDS2 + n] + b2[n];
            out[OFF_CONF + gi] = sigmoidf_(s);
        }
    }
}

// ---------------------------------------------------------------------------
// Launch
// ---------------------------------------------------------------------------
extern "C" void kernel_launch(void* const* d_in, const int* in_sizes, int n_in,
                              void* d_out, int out_size) {
    const float* features = (const float*)d_in[0];
    const float* grid     = (const float*)d_in[1];
    const float* anc      = (const float*)d_in[2];
    const float* bboxes   = (const float*)d_in[3];
    const int*   pos      = (const int*)d_in[4];
    const int*   neg      = (const int*)d_in[5];
    const float* W1       = (const float*)d_in[6];
    const float* b1       = (const float*)d_in[7];
    const float* W2       = (const float*)d_in[8];
    const float* b2       = (const float*)d_in[9];
    float* out = (float*)d_out;

    prep_kernel<<<PREP_BLKS, 256>>>(features, W1, W2, grid, anc, bboxes,
                                    pos, neg, out);

    cudaFuncSetAttribute(gemm_wmma_kernel,
                         cudaFuncAttributeMaxDynamicSharedMemorySize,
                         SMEM_GEMM_BYTES);
    gemm_wmma_kernel<<<MTOT / 64, 512, SMEM_GEMM_BYTES>>>(pos, neg, b1, b2, out);
}

// round 17
// speedup vs baseline: 1.4962x; 1.0189x over previous
#include <cuda_runtime.h>
#include <cuda_bf16.h>
#include <mma.h>
#include <math.h>
#include <stdint.h>

using namespace nvcuda;

// ---------------- problem constants ----------------
#define B_    32
#define CIN   1280
#define HH    28
#define WW    28
#define HW    784
#define A_    9
#define HID   128
#define M_    4096
#define MTOT  8192
#define AHW   7056
#define NPOS  (B_ * HW)        // 25088

// output layout
#define OFF_CONF   0
#define OFF_OFFS   8192
#define OFF_CLASS  24576
#define OFF_IOU    106496

// ---------------- scratch ----------------
__device__ __nv_bfloat16 g_fT_hi[(size_t)NPOS * CIN];   // [b*HW+p][k]
__device__ __nv_bfloat16 g_fT_lo[(size_t)NPOS * CIN];
__device__ __nv_bfloat16 g_W1hi[HID * CIN];             // [n][k]
__device__ __nv_bfloat16 g_W1lo[HID * CIN];
__device__ __nv_bfloat16 g_W2hi[80 * HID];              // rows 65..79 stay zero
__device__ __nv_bfloat16 g_W2lo[80 * HID];

// ---------------- helpers ----------------
__device__ __forceinline__ uint32_t smem_u32(const void* p) {
    uint32_t a;
    asm("{ .reg .u64 t; cvta.to.shared.u64 t, %1; cvt.u32.u64 %0, t; }"
        : "=r"(a) : "l"(p));
    return a;
}
__device__ __forceinline__ uint32_t PK(__nv_bfloat16 a, __nv_bfloat16 b) {
    unsigned short ua = *(unsigned short*)&a;
    unsigned short ub = *(unsigned short*)&b;
    return (uint32_t)ua | ((uint32_t)ub << 16);
}
__device__ __forceinline__ void cpa16(uint32_t dst, const void* src) {
    asm volatile("cp.async.ca.shared.global [%0], [%1], 16;" :: "r"(dst), "l"(src));
}
#define CP_COMMIT() asm volatile("cp.async.commit_group;" ::: "memory")
#define CP_WAIT0()  asm volatile("cp.async.wait_group 0;" ::: "memory")
#define CP_WAIT1()  asm volatile("cp.async.wait_group 1;" ::: "memory")
#define CP_WAIT2()  asm volatile("cp.async.wait_group 2;" ::: "memory")

__device__ __forceinline__ float sigmoidf_(float x) {
    return 1.0f / (1.0f + expf(-x));
}

// ---------------------------------------------------------------------------
// Kernel 1: fused prep.
//   transpose: 3-buffer cp.async ring (distance 2), SWIZZLED tile layout
//     (row-rotated 16B blocks) -> conflict-free LDS in the store phase.
//   IoU: phase-A per-j box precompute, phase-B n-stream
//   + W1/W2 splits
// ---------------------------------------------------------------------------
#define TR_BLKS  (25 * 32)          // 800
#define IOU_BLKS (56 * 32)          // 1792
#define W1_BLKS  160
#define W2_BLKS  9
#define PREP_BLKS (TR_BLKS + IOU_BLKS + W1_BLKS + W2_BLKS)

__global__ void __launch_bounds__(256)
prep_kernel(const float* __restrict__ feat,
            const float* __restrict__ W1,
            const float* __restrict__ W2,
            const float* __restrict__ grid,
            const float* __restrict__ anc,
            const float* __restrict__ bboxes,
            const int* __restrict__ pos,
            const int* __restrict__ neg,
            float* __restrict__ out) {
    const int bid = blockIdx.x;
    const int t   = threadIdx.x;

    if (bid < TR_BLKS) {
        // ---- transpose + bf16 split (3-buffer ring, swizzled, TLD=32) ----
        // logical tile[k][p] (64 x 32 floats); element [r][c] stored at
        // physical col ((c & ~3) + 4*(r>>3) + (c & 3)) & 31 within row r.
        __shared__ float tile[3][64][32];
        __shared__ unsigned char sflag[32];
        const int pt = bid % 25;
        const int b  = bid / 25;
        const int p0 = pt * 32;

        if (t < 32) sflag[t] = 0;
        __syncthreads();
#pragma unroll 4
        for (int i = t; i < MTOT; i += 256) {
            int idx = (i < M_) ? pos[i] : neg[i - M_];
            int p  = idx % HW;
            int bb = idx / (HW * A_);
            int d  = p - p0;
            if (bb == b && ((unsigned)d < 32u)) sflag[d] = 1;
        }

        uint32_t tb[3];
        tb[0] = smem_u32(&tile[0][0][0]);
        tb[1] = smem_u32(&tile[1][0][0]);
        tb[2] = smem_u32(&tile[2][0][0]);
        const float* fb = feat + (size_t)b * CIN * HW;

        const int kk0 = t >> 3;            // k row phase (0..31)
        const int j4  = (t & 7) * 4;       // logical p block offset
        const int p   = p0 + j4;
        const bool inb = (p + 3 < HW);

        // swizzled dst cols for the two row phases (kk0 and kk0+32)
        const int pc0 = (j4 + 4 * ((kk0      ) >> 3)) & 31;
        const int pc1 = (j4 + 4 * ((kk0 + 32) >> 3)) & 31;

        // prologue: issue kt=0 (buf0), kt=1 (buf1)
#pragma unroll
        for (int pre = 0; pre < 2; pre++) {
            if (inb) {
                cpa16(tb[pre] + (kk0 * 32 + pc0) * 4,
                      fb + (size_t)(pre * 64 + kk0) * HW + p);
                cpa16(tb[pre] + ((kk0 + 32) * 32 + pc1) * 4,
                      fb + (size_t)(pre * 64 + kk0 + 32) * HW + p);
            } else {
                *(float4*)&tile[pre][kk0][pc0]      = make_float4(0.f, 0.f, 0.f, 0.f);
                *(float4*)&tile[pre][kk0 + 32][pc1] = make_float4(0.f, 0.f, 0.f, 0.f);
            }
            CP_COMMIT();
        }
        __syncthreads();   // flags visible

        const int pr = t >> 3;        // store-phase p (0..31)
        const int gq = t & 7;         // store-phase k-group (0..7)
        const bool dostore = sflag[pr];
        // physical col of logical col pr for rows gq*8..gq*8+7 (r>>3 == gq):
        const int rc = ((pr & ~3) + 4 * gq + (pr & 3)) & 31;

        for (int kt = 0; kt < 20; kt++) {
            const int buf = kt % 3;
            if (kt + 2 < 20) {
                int bn = (kt + 2) % 3;
                const int k0n = (kt + 2) * 64;
                if (inb) {
                    cpa16(tb[bn] + (kk0 * 32 + pc0) * 4,
                          fb + (size_t)(k0n + kk0) * HW + p);
                    cpa16(tb[bn] + ((kk0 + 32) * 32 + pc1) * 4,
                          fb + (size_t)(k0n + kk0 + 32) * HW + p);
                } else {
                    *(float4*)&tile[bn][kk0][pc0]      = make_float4(0.f, 0.f, 0.f, 0.f);
                    *(float4*)&tile[bn][kk0 + 32][pc1] = make_float4(0.f, 0.f, 0.f, 0.f);
                }
                CP_COMMIT();
                CP_WAIT2();
            } else if (kt + 1 < 20) {
                CP_WAIT1();
            } else {
                CP_WAIT0();
            }
            __syncthreads();

            if (dostore) {
                const float (*tl)[32] = tile[buf];
                const int k0 = kt * 64;
                size_t base = (size_t)(b * HW + p0 + pr) * CIN + k0 + gq * 8;
                uint32_t hiw[4], low[4];
#pragma unroll
                for (int i2 = 0; i2 < 4; i2++) {
                    float v0 = tl[gq * 8 + i2 * 2 + 0][rc];
                    float v1 = tl[gq * 8 + i2 * 2 + 1][rc];
                    __nv_bfloat16 h0 = __float2bfloat16(v0);
                    __nv_bfloat16 h1 = __float2bfloat16(v1);
                    hiw[i2] = PK(h0, h1);
                    low[i2] = PK(__float2bfloat16(v0 - __bfloat162float(h0)),
                                 __float2bfloat16(v1 - __bfloat162float(h1)));
                }
                *(uint4*)&g_fT_hi[base] = make_uint4(hiw[0], hiw[1], hiw[2], hiw[3]);
                *(uint4*)&g_fT_lo[base] = make_uint4(low[0], low[1], low[2], low[3]);
            }
            __syncthreads();
        }
        return;
    }

    if (bid < TR_BLKS + IOU_BLKS) {
        // ---- IoU: phase A computes per-j boxes once; phase B streams n ----
        __shared__ float s_x1[64], s_y1[64], s_x2[64], s_y2[64], s_sb[64];
        __shared__ float j_x1[128], j_y1[128], j_x2[128], j_y2[128], j_sp[128];
        int r  = bid - TR_BLKS;
        int bx = r % 56;
        int b  = r / 56;
        const int j0 = bx * 128;

        if (t < 64) {
            const float* bb = bboxes + ((size_t)b * 64 + t) * 5;
            float x1 = bb[0], y1 = bb[1], x2 = bb[2], y2 = bb[3];
            s_x1[t] = x1; s_y1[t] = y1; s_x2[t] = x2; s_y2[t] = y2;
            float sb = (x2 - x1) * (y2 - y1);
            s_sb[t] = (x1 < 0.0f) ? 0.0f : sb;
        }
        if (t < 128) {
            int j = j0 + t;
            if (j < AHW) {
                int a  = j / HW;
                int rr = j - a * HW;
                int h  = rr / WW;
                int w  = rr - h * WW;
                float cx = grid[(((size_t)b * HH + h) * WW + w) * 2 + 0];
                float cy = grid[(((size_t)b * HH + h) * WW + w) * 2 + 1];
                float hw2 = anc[a * 2 + 0] * 0.5f;
                float hh2 = anc[a * 2 + 1] * 0.5f;
                j_x1[t] = cx - hw2; j_y1[t] = cy - hh2;
                j_x2[t] = cx + hw2; j_y2[t] = cy + hh2;
                j_sp[t] = (hw2 * 2.0f) * (hh2 * 2.0f);
            }
        }
        __syncthreads();

        const int n4   = (t & 15) * 4;
        const int jrow = t >> 4;          // 0..15

        float bx1[4], by1[4], bx2[4], by2[4], sb4[4];
#pragma unroll
        for (int i = 0; i < 4; i++) {
            bx1[i] = s_x1[n4 + i]; by1[i] = s_y1[n4 + i];
            bx2[i] = s_x2[n4 + i]; by2[i] = s_y2[n4 + i];
            sb4[i] = s_sb[n4 + i];
        }

#pragma unroll
        for (int it = 0; it < 8; it++) {
            int sj = it * 16 + jrow;
            int j  = j0 + sj;
            if (j >= AHW) break;
            float px1 = j_x1[sj], py1 = j_y1[sj];
            float px2 = j_x2[sj], py2 = j_y2[sj];
            float sp  = j_sp[sj];

            float4 v;
            float* vp = &v.x;
#pragma unroll
            for (int i = 0; i < 4; i++) {
                float ix1 = fmaxf(px1, bx1[i]);
                float iy1 = fmaxf(py1, by1[i]);
                float ix2 = fminf(px2, bx2[i]);
                float iy2 = fminf(py2, by2[i]);
                float si  = fmaxf(ix2 - ix1, 0.0f) * fmaxf(iy2 - iy1, 0.0f);
                float su  = sp + sb4[i] - si;
                vp[i] = (su <= 0.0f || sp <= 0.0f || sb4[i] <= 0.0f)
                        ? 0.0f : fmaxf(si / (su + 1e-8f), 0.0f);
            }
            *(float4*)&out[OFF_IOU + ((size_t)b * AHW + j) * 64 + n4] = v;
        }
        return;
    }

    if (bid < TR_BLKS + IOU_BLKS + W1_BLKS) {
        int i4 = (bid - TR_BLKS - IOU_BLKS) * 256 + t;
        const float4 v = ((const float4*)W1)[i4];
        __nv_bfloat16 h0 = __float2bfloat16(v.x), h1 = __float2bfloat16(v.y);
        __nv_bfloat16 h2 = __float2bfloat16(v.z), h3 = __float2bfloat16(v.w);
        ((uint2*)g_W1hi)[i4] = make_uint2(PK(h0, h1), PK(h2, h3));
        ((uint2*)g_W1lo)[i4] = make_uint2(
            PK(__float2bfloat16(v.x - __bfloat162float(h0)),
               __float2bfloat16(v.y - __bfloat162float(h1))),
            PK(__float2bfloat16(v.z - __bfloat162float(h2)),
               __float2bfloat16(v.w - __bfloat162float(h3))));
        return;
    }

    {
        int i4 = (bid - TR_BLKS - IOU_BLKS - W1_BLKS) * 256 + t;
        if (i4 < (65 * HID) / 4) {
            const float4 v = ((const float4*)W2)[i4];
            __nv_bfloat16 h0 = __float2bfloat16(v.x), h1 = __float2bfloat16(v.y);
            __nv_bfloat16 h2 = __float2bfloat16(v.z), h3 = __float2bfloat16(v.w);
            ((uint2*)g_W2hi)[i4] = make_uint2(PK(h0, h1), PK(h2, h3));
            ((uint2*)g_W2lo)[i4] = make_uint2(
                PK(__float2bfloat16(v.x - __bfloat162float(h0)),
                   __float2bfloat16(v.y - __bfloat162float(h1))),
                PK(__float2bfloat16(v.z - __bfloat162float(h2)),
                   __float2bfloat16(v.w - __bfloat162float(h3))));
        }
    }
}

// ---------------------------------------------------------------------------
// Kernel 2: gathered WMMA GEMM + fused head epilogue.
//   EXACT R9 config (proven optimum). DO NOT TOUCH.
// ---------------------------------------------------------------------------
#define LDA 72
#define LDB 72
#define NCHUNK 20
#define SA_HI 0
#define SA_LO (64 * LDA)
#define SB_HI (2 * 64 * LDA)
#define SB_LO (2 * 64 * LDA + 128 * LDB)
#define STAGE_ELEMS (2 * 64 * LDA + 2 * 128 * LDB)   // 27648
#define NSTAGE 3
#define SMEM_GEMM_BYTES (NSTAGE * STAGE_ELEMS * 2)   // 165888

#define LDS_STAGE 132
#define H_HI_OFF  34816
#define H_LO_OFF  52224
#define LDH       136
#define W2HI_OFF  69632
#define W2LO_OFF  91392
#define LDW2      136
#define ST2_OFF   113152
#define LDS2      84

extern __shared__ __nv_bfloat16 smem_g[];

__device__ __forceinline__ void gemm_issue(uint32_t sbase, int k0,
                                           const int* __restrict__ srow, int t) {
    {
        int row = t >> 3;
        int j   = t & 7;
        size_t src = (size_t)srow[row] * CIN + k0 + j * 8;
        cpa16(sbase + (SA_HI + row * LDA + j * 8) * 2, g_fT_hi + src);
        cpa16(sbase + (SA_LO + row * LDA + j * 8) * 2, g_fT_lo + src);
    }
#pragma unroll
    for (int h = 0; h < 2; h++) {
        int q = t + h * 512;
        int n = q >> 3;
        int j = q & 7;
        size_t src = (size_t)n * CIN + k0 + j * 8;
        cpa16(sbase + (SB_HI + n * LDB + j * 8) * 2, g_W1hi + src);
        cpa16(sbase + (SB_LO + n * LDB + j * 8) * 2, g_W1lo + src);
    }
}

__global__ void __launch_bounds__(512, 1)
gemm_wmma_kernel(const int* __restrict__ pos,
                 const int* __restrict__ neg,
                 const float* __restrict__ b1,
                 const float* __restrict__ b2,
                 float* __restrict__ out) {
    __shared__ int srow[64];
    __shared__ int sanc[64];

    const int t   = threadIdx.x;
    const int wid = t >> 5;
    const int i0  = blockIdx.x * 64;
    const bool isneg = (i0 >= M_);

    if (t < 64) {
        int gi  = i0 + t;
        int idx = (gi < M_) ? pos[gi] : neg[gi - M_];
        int p   = idx % HW;
        int ba  = idx / HW;
        srow[t] = (ba / A_) * HW + p;
        sanc[t] = ba % A_;
    }
    __syncthreads();

    const uint32_t sb = smem_u32(smem_g);

    const int wr = wid >> 2;
    const int wc = wid & 3;

    wmma::fragment<wmma::accumulator, 16, 16, 16, float> acc[2];
#pragma unroll
    for (int nt = 0; nt < 2; nt++) wmma::fill_fragment(acc[nt], 0.0f);

    gemm_issue(sb, 0, srow, t);
    CP_COMMIT();
    gemm_issue(sb + STAGE_ELEMS * 2, 64, srow, t);
    CP_COMMIT();

    int stg = 0;
    for (int c = 0; c < NCHUNK; c++) {
        if (c + 2 < NCHUNK) {
            int s2 = stg + 2; if (s2 >= NSTAGE) s2 -= NSTAGE;
            gemm_issue(sb + s2 * STAGE_ELEMS * 2, (c + 2) * 64, srow, t);
            CP_COMMIT();
            CP_WAIT2();
        } else if (c + 1 < NCHUNK) {
            CP_WAIT1();
        } else {
            CP_WAIT0();
        }
        __syncthreads();

        const __nv_bfloat16* buf = smem_g + stg * STAGE_ELEMS;
#pragma unroll
        for (int ks = 0; ks < 4; ks++) {
            wmma::fragment<wmma::matrix_a, 16, 16, 16, __nv_bfloat16, wmma::row_major> a_hi, a_lo;
            wmma::load_matrix_sync(a_hi, buf + SA_HI + (wr * 16) * LDA + ks * 16, LDA);
            wmma::load_matrix_sync(a_lo, buf + SA_LO + (wr * 16) * LDA + ks * 16, LDA);
#pragma unroll
            for (int nt = 0; nt < 2; nt++) {
                int n = wc * 32 + nt * 16;
                wmma::fragment<wmma::matrix_b, 16, 16, 16, __nv_bfloat16, wmma::col_major> b_hi, b_lo;
                wmma::load_matrix_sync(b_hi, buf + SB_HI + n * LDB + ks * 16, LDB);
                wmma::load_matrix_sync(b_lo, buf + SB_LO + n * LDB + ks * 16, LDB);
                wmma::mma_sync(acc[nt], a_hi, b_hi, acc[nt]);
                wmma::mma_sync(acc[nt], a_hi, b_lo, acc[nt]);
                wmma::mma_sync(acc[nt], a_lo, b_hi, acc[nt]);
            }
        }
        __syncthreads();
        if (++stg == NSTAGE) stg = 0;
    }

    // epilogue 1: accum -> stage (fp32)
    float* stage = (float*)smem_g;
#pragma unroll
    for (int nt = 0; nt < 2; nt++) {
        wmma::store_matrix_sync(&stage[(wr * 16) * LDS_STAGE + wc * 32 + nt * 16],
                                acc[nt], LDS_STAGE, wmma::mem_row_major);
    }
    __syncthreads();

    // epilogue 2: h -> bf16 hi/lo; W2 -> smem
    __nv_bfloat16* hhi  = (__nv_bfloat16*)((char*)smem_g + H_HI_OFF);
    __nv_bfloat16* hlo  = (__nv_bfloat16*)((char*)smem_g + H_LO_OFF);
    __nv_bfloat16* w2hi = (__nv_bfloat16*)((char*)smem_g + W2HI_OFF);
    __nv_bfloat16* w2lo = (__nv_bfloat16*)((char*)smem_g + W2LO_OFF);

    for (int i = t; i < 64 * 32; i += 512) {
        int row = i >> 5;
        int c4  = (i & 31) * 4;
        float4 v = *(float4*)&stage[row * LDS_STAGE + c4];
        v.x += b1[c4 + 0]; v.y += b1[c4 + 1]; v.z += b1[c4 + 2]; v.w += b1[c4 + 3];
        v.x = (v.x > 0.f) ? v.x : 0.01f * v.x;
        v.y = (v.y > 0.f) ? v.y : 0.01f * v.y;
        v.z = (v.z > 0.f) ? v.z : 0.01f * v.z;
        v.w = (v.w > 0.f) ? v.w : 0.01f * v.w;
        __nv_bfloat16 h0 = __float2bfloat16(v.x), h1 = __float2bfloat16(v.y);
        __nv_bfloat16 h2 = __float2bfloat16(v.z), h3 = __float2bfloat16(v.w);
        *(uint2*)&hhi[row * LDH + c4] = make_uint2(PK(h0, h1), PK(h2, h3));
        *(uint2*)&hlo[row * LDH + c4] = make_uint2(
            PK(__float2bfloat16(v.x - __bfloat162float(h0)),
               __float2bfloat16(v.y - __bfloat162float(h1))),
            PK(__float2bfloat16(v.z - __bfloat162float(h2)),
               __float2bfloat16(v.w - __bfloat162float(h3))));
    }
    for (int q = t; q < 80 * 16; q += 512) {
        int n = q >> 4;
        int j = q & 15;
        *(uint4*)&w2hi[n * LDW2 + j * 8] = *(const uint4*)&g_W2hi[n * HID + j * 8];
        *(uint4*)&w2lo[n * LDW2 + j * 8] = *(const uint4*)&g_W2lo[n * HID + j * 8];
    }
    __syncthreads();

    // epilogue 3: D2[64 x 80] = H @ W2^T
    float* stage2 = (float*)((char*)smem_g + ST2_OFF);
    const int ntile = isneg ? 12 : 20;
    for (int tid = wid; tid < ntile; tid += 16) {
        int wr2 = tid & 3;
        int wc2 = tid >> 2;
        wmma::fragment<wmma::accumulator, 16, 16, 16, float> acc2;
        wmma::fill_fragment(acc2, 0.0f);
#pragma unroll
        for (int ks = 0; ks < 8; ks++) {
            wmma::fragment<wmma::matrix_a, 16, 16, 16, __nv_bfloat16, wmma::row_major> a_hi, a_lo;
            wmma::load_matrix_sync(a_hi, &hhi[(wr2 * 16) * LDH + ks * 16], LDH);
            wmma::load_matrix_sync(a_lo, &hlo[(wr2 * 16) * LDH + ks * 16], LDH);
            wmma::fragment<wmma::matrix_b, 16, 16, 16, __nv_bfloat16, wmma::col_major> b_hi, b_lo;
            wmma::load_matrix_sync(b_hi, &w2hi[(wc2 * 16) * LDW2 + ks * 16], LDW2);
            wmma::load_matrix_sync(b_lo, &w2lo[(wc2 * 16) * LDW2 + ks * 16], LDW2);
            wmma::mma_sync(acc2, a_hi, b_hi, acc2);
            wmma::mma_sync(acc2, a_hi, b_lo, acc2);
            wmma::mma_sync(acc2, a_lo, b_hi, acc2);
        }
        wmma::store_matrix_sync(&stage2[(wr2 * 16) * LDS2 + wc2 * 16],
                                acc2, LDS2, wmma::mem_row_major);
    }
    __syncthreads();

    // epilogue 4: output mapping
    if (!isneg) {
        for (int e = t; e < 64 * 25; e += 512) {
            int row = e / 25;
            int q   = e - row * 25;
            int gi  = i0 + row;
            int a   = sanc[row];
            if (q == 0) {
                int n = 5 * a;
                float s = stage2[row * LDS2 + n] + b2[n];
                out[OFF_CONF + gi] = sigmoidf_(s);
            } else if (q <= 4) {
                int n = 5 * a + q;
                float s = stage2[row * LDS2 + n] + b2[n];
                out[OFF_OFFS + gi * 4 + (q - 1)] = (q <= 2) ? (sigmoidf_(s) - 0.5f) : s;
            } else {
                int n = 40 + q;
                float s = stage2[row * LDS2 + n] + b2[n];
                out[OFF_CLASS + gi * 20 + (q - 5)] = s;
            }
        }
    } else {
        if (t < 64) {
            int gi = i0 + t;
            int n  = 5 * sanc[t];
            float s = stage2[t * LDS2 + n] + b2[n];
            out[OFF_CONF + gi] = sigmoidf_(s);
        }
    }
}

// ---------------------------------------------------------------------------
// Launch
// ---------------------------------------------------------------------------
extern "C" void kernel_launch(void* const* d_in, const int* in_sizes, int n_in,
                              void* d_out, int out_size) {
    const float* features = (const float*)d_in[0];
    const float* grid     = (const float*)d_in[1];
    const float* anc      = (const float*)d_in[2];
    const float* bboxes   = (const float*)d_in[3];
    const int*   pos      = (const int*)d_in[4];
    const int*   neg      = (const int*)d_in[5];
    const float* W1       = (const float*)d_in[6];
    const float* b1       = (const float*)d_in[7];
    const float* W2       = (const float*)d_in[8];
    const float* b2       = (const float*)d_in[9];
    float* out = (float*)d_out;

    prep_kernel<<<PREP_BLKS, 256>>>(features, W1, W2, grid, anc, bboxes,
                                    pos, neg, out);

    cudaFuncSetAttribute(gemm_wmma_kernel,
                         cudaFuncAttributeMaxDynamicSharedMemorySize,
                         SMEM_GEMM_BYTES);
    gemm_wmma_kernel<<<MTOT / 64, 512, SMEM_GEMM_BYTES>>>(pos, neg, b1, b2, out);
}